// round 11
// baseline (speedup 1.0000x reference)
#include <cuda_runtime.h>
#include <cstdint>

// Problem constants
#define B_  8
#define S_  1024
#define C_  768
#define H_  12
#define D_  64
#define BS_ (B_ * S_)            // 8192
#define BHSD (B_ * H_ * S_ * D_) // 6291456

// Scratch (allocation-free: static device globals)
__device__ float g_q[BHSD];
__device__ float g_k[BHSD];
__device__ float g_v[BHSD];
__device__ float g_y[BS_ * C_];

// ---------------------------------------------------------------------------
// mma.sync tf32 helpers (base sm_103 ISA)
// ---------------------------------------------------------------------------
__device__ __forceinline__ uint32_t f2tf32(float f) {
    uint32_t r;
    asm("cvt.rna.tf32.f32 %0, %1;" : "=r"(r) : "f"(f));
    return r;
}
__device__ __forceinline__ float fexp2(float x) {
    float y;
    asm("ex2.approx.f32 %0, %1;" : "=f"(y) : "f"(x));
    return y;
}
__device__ __forceinline__ void mma_tf32(float* c, const uint32_t* a,
                                         const uint32_t* b) {
    asm volatile(
        "mma.sync.aligned.m16n8k8.row.col.f32.tf32.tf32.f32 "
        "{%0,%1,%2,%3}, {%4,%5,%6,%7}, {%8,%9}, {%0,%1,%2,%3};"
        : "+f"(c[0]), "+f"(c[1]), "+f"(c[2]), "+f"(c[3])
        : "r"(a[0]), "r"(a[1]), "r"(a[2]), "r"(a[3]), "r"(b[0]), "r"(b[1]));
}
__device__ __forceinline__ void sts_tf32(uint32_t* dst, float4 v) {
    uint4 u = make_uint4(f2tf32(v.x), f2tf32(v.y), f2tf32(v.z), f2tf32(v.w));
    *(uint4*)dst = u;
}

// ===========================================================================
// PIPELINED GEMM (R9, ncu-verified faster for the big QKV GEMM).
// Double-buffered smem, 1 barrier per 32-K chunk. MODE 0 only here.
// ===========================================================================
#define CW (128 * 36)
#define GEMM_SMEM_BYTES (4 * CW * 4)  // 73728
#define NKC (C_ / 32)                 // 24

template <int KS0>
__device__ __forceinline__ void gemm_compute2(
    const uint32_t* __restrict__ Ac, const uint32_t* __restrict__ Bc,
    float (&acc)[4][4][4], int wr, int wc, int g, int t)
{
    #pragma unroll
    for (int ks = KS0; ks < KS0 + 2; ks++) {
        const int kc = ks * 8;
        uint32_t af[4][4], bf[4][2];
        #pragma unroll
        for (int mt = 0; mt < 4; mt++) {
            const int r = wr + mt * 16 + g;
            af[mt][0] = Ac[r * 36 + kc + t];
            af[mt][1] = Ac[(r + 8) * 36 + kc + t];
            af[mt][2] = Ac[r * 36 + kc + t + 4];
            af[mt][3] = Ac[(r + 8) * 36 + kc + t + 4];
        }
        #pragma unroll
        for (int nt = 0; nt < 4; nt++) {
            const int n = wc + nt * 8 + g;
            bf[nt][0] = Bc[n * 36 + kc + t];
            bf[nt][1] = Bc[n * 36 + kc + t + 4];
        }
        #pragma unroll
        for (int mt = 0; mt < 4; mt++)
            #pragma unroll
            for (int nt = 0; nt < 4; nt++)
                mma_tf32(acc[mt][nt], af[mt], bf[nt]);
    }
}

__global__ __launch_bounds__(256, 2) void mmagemm_pipe0(
    const float* __restrict__ A, const float* __restrict__ Bm,
    const float* __restrict__ bias)
{
    extern __shared__ uint32_t sg[];

    const int tid  = threadIdx.x;
    const int wid  = tid >> 5;
    const int lane = tid & 31;
    const int g = lane >> 2;
    const int t = lane & 3;
    const int wr = (wid >> 2) * 64;
    const int wc = (wid & 3) * 32;
    const int bm = blockIdx.y * 128;
    const int bn = blockIdx.x * 128;

    int rowi[4], f4i[4];
    const float *Ap[4], *Bp[4];
    #pragma unroll
    for (int i = 0; i < 4; i++) {
        const int idx = tid + i * 256;
        rowi[i] = idx >> 3;
        f4i[i]  = (idx & 7) << 2;
        Ap[i] = A  + (size_t)(bm + rowi[i]) * C_ + f4i[i];
        Bp[i] = Bm + (size_t)(bn + rowi[i]) * C_ + f4i[i];
    }

    float acc[4][4][4];
    #pragma unroll
    for (int i = 0; i < 4; i++)
        #pragma unroll
        for (int j = 0; j < 4; j++)
            #pragma unroll
            for (int r = 0; r < 4; r++) acc[i][j][r] = 0.f;

    #pragma unroll
    for (int i = 0; i < 4; i++) {
        float4 va = *(const float4*)(Ap[i]);
        float4 vb = *(const float4*)(Bp[i]);
        sts_tf32(sg      + rowi[i] * 36 + f4i[i], va);
        sts_tf32(sg + CW + rowi[i] * 36 + f4i[i], vb);
    }
    __syncthreads();

    for (int kc = 0; kc < NKC; kc++) {
        uint32_t* Ac = sg + (kc & 1) * (2 * CW);
        uint32_t* Bc = Ac + CW;
        uint32_t* An = sg + ((kc & 1) ^ 1) * (2 * CW);
        uint32_t* Bn = An + CW;
        const bool pf = (kc < NKC - 1);
        const int k1 = (kc + 1) * 32;

        float4 va[2], vb[2];
        if (pf) {
            va[0] = *(const float4*)(Ap[0] + k1);
            va[1] = *(const float4*)(Ap[1] + k1);
            vb[0] = *(const float4*)(Bp[0] + k1);
            vb[1] = *(const float4*)(Bp[1] + k1);
        }
        gemm_compute2<0>(Ac, Bc, acc, wr, wc, g, t);
        if (pf) {
            sts_tf32(An + rowi[0] * 36 + f4i[0], va[0]);
            sts_tf32(An + rowi[1] * 36 + f4i[1], va[1]);
            sts_tf32(Bn + rowi[0] * 36 + f4i[0], vb[0]);
            sts_tf32(Bn + rowi[1] * 36 + f4i[1], vb[1]);
            va[0] = *(const float4*)(Ap[2] + k1);
            va[1] = *(const float4*)(Ap[3] + k1);
            vb[0] = *(const float4*)(Bp[2] + k1);
            vb[1] = *(const float4*)(Bp[3] + k1);
        }
        gemm_compute2<2>(Ac, Bc, acc, wr, wc, g, t);
        if (pf) {
            sts_tf32(An + rowi[2] * 36 + f4i[2], va[0]);
            sts_tf32(An + rowi[3] * 36 + f4i[3], va[1]);
            sts_tf32(Bn + rowi[2] * 36 + f4i[2], vb[0]);
            sts_tf32(Bn + rowi[3] * 36 + f4i[3], vb[1]);
        }
        __syncthreads();
    }

    // Epilogue: scatter to g_q/g_k/g_v with bias (validated)
    #pragma unroll
    for (int mt = 0; mt < 4; mt++) {
        #pragma unroll
        for (int nt = 0; nt < 4; nt++) {
            const int col = wc + nt * 8 + 2 * t;
            const int r0  = bm + wr + mt * 16 + g;
            const int r1  = r0 + 8;
            const float bv0 = bias[bn + col];
            const float bv1 = bias[bn + col + 1];
            float2 lo = make_float2(acc[mt][nt][0] + bv0, acc[mt][nt][1] + bv1);
            float2 hi = make_float2(acc[mt][nt][2] + bv0, acc[mt][nt][3] + bv1);
            const int comp = bn / C_;
            float* db = (comp == 0) ? g_q : (comp == 1) ? g_k : g_v;
            const int c = bn - comp * C_ + col;
            const int h = c >> 6, d = c & 63;
            {
                const int b = r0 >> 10, s = r0 & 1023;
                *(float2*)(db + (size_t)(b * H_ + h) * (S_ * D_) +
                           (size_t)s * D_ + d) = lo;
            }
            {
                const int b = r1 >> 10, s = r1 & 1023;
                *(float2*)(db + (size_t)(b * H_ + h) * (S_ * D_) +
                           (size_t)s * D_ + d) = hi;
            }
        }
    }
}

// ===========================================================================
// SINGLE-BUFFERED GEMM (R4/R8 version, known-good): output projection.
// ===========================================================================
__global__ __launch_bounds__(256) void mmagemm_sb1(
    const float* __restrict__ Bm, const float* __restrict__ bias,
    float* __restrict__ Cout)
{
    __shared__ uint32_t As[128][36];
    __shared__ uint32_t Bs[128][36];

    const float* A = (const float*)g_y;

    const int tid  = threadIdx.x;
    const int wid  = tid >> 5;
    const int lane = tid & 31;
    const int g = lane >> 2;
    const int t = lane & 3;
    const int wr = (wid >> 2) * 64;
    const int wc = (wid & 3) * 32;
    const int bm = blockIdx.y * 128;
    const int bn = blockIdx.x * 128;

    float acc[4][4][4];
    #pragma unroll
    for (int i = 0; i < 4; i++)
        #pragma unroll
        for (int j = 0; j < 4; j++)
            #pragma unroll
            for (int r = 0; r < 4; r++) acc[i][j][r] = 0.f;

    for (int k0 = 0; k0 < C_; k0 += 32) {
        #pragma unroll
        for (int i = 0; i < 4; i++) {
            const int idx = tid + i * 256;
            const int row = idx >> 3;
            const int f4  = (idx & 7) << 2;
            float4 va = *(const float4*)(A  + (size_t)(bm + row) * C_ + k0 + f4);
            float4 vb = *(const float4*)(Bm + (size_t)(bn + row) * C_ + k0 + f4);
            sts_tf32(&As[row][f4], va);
            sts_tf32(&Bs[row][f4], vb);
        }
        __syncthreads();

        #pragma unroll
        for (int ks = 0; ks < 4; ks++) {
            const int kc = ks * 8;
            uint32_t af[4][4], bf[4][2];
            #pragma unroll
            for (int mt = 0; mt < 4; mt++) {
                const int r = wr + mt * 16 + g;
                af[mt][0] = As[r][kc + t];
                af[mt][1] = As[r + 8][kc + t];
                af[mt][2] = As[r][kc + t + 4];
                af[mt][3] = As[r + 8][kc + t + 4];
            }
            #pragma unroll
            for (int nt = 0; nt < 4; nt++) {
                const int n = wc + nt * 8 + g;
                bf[nt][0] = Bs[n][kc + t];
                bf[nt][1] = Bs[n][kc + t + 4];
            }
            #pragma unroll
            for (int mt = 0; mt < 4; mt++)
                #pragma unroll
                for (int nt = 0; nt < 4; nt++)
                    mma_tf32(acc[mt][nt], af[mt], bf[nt]);
        }
        __syncthreads();
    }

    #pragma unroll
    for (int mt = 0; mt < 4; mt++) {
        #pragma unroll
        for (int nt = 0; nt < 4; nt++) {
            const int col = wc + nt * 8 + 2 * t;
            const int r0  = bm + wr + mt * 16 + g;
            const int r1  = r0 + 8;
            const float bv0 = bias[bn + col];
            const float bv1 = bias[bn + col + 1];
            *(float2*)(Cout + (size_t)r0 * C_ + bn + col) =
                make_float2(acc[mt][nt][0] + bv0, acc[mt][nt][1] + bv1);
            *(float2*)(Cout + (size_t)r1 * C_ + bn + col) =
                make_float2(acc[mt][nt][2] + bv0, acc[mt][nt][3] + bv1);
        }
    }
}

// ===========================================================================
// Flash attention (unchanged from R8 — passing): mma QK^T -> S spill ->
// in-place SIMT softmax -> mma P@V. grid (8, 96), 256 threads.
// ===========================================================================
#define AT_SQ   0
#define AT_SK   (128 * 68)
#define AT_SV   (AT_SK + 32 * 68)
#define AT_SS   (AT_SV + 32 * 72)
#define AT_SFAC (AT_SS + 128 * 36)
#define AT_SL   (AT_SFAC + 128)
#define AT_SMEM_WORDS (AT_SL + 128)
#define AT_SMEM_BYTES (AT_SMEM_WORDS * 4)       // 72192
#define QSCALE 0.18033688011f                   // 0.125 * log2(e)

__global__ __launch_bounds__(256) void attn_mma(const int* __restrict__ mask)
{
    extern __shared__ uint32_t su[];
    uint32_t (*sQ)[68]  = (uint32_t(*)[68])(su + AT_SQ);
    uint32_t (*sK)[68]  = (uint32_t(*)[68])(su + AT_SK);
    uint32_t (*sV)[72]  = (uint32_t(*)[72])(su + AT_SV);
    float    (*sSP)[36] = (float(*)[36])(su + AT_SS);
    float* sFac = (float*)(su + AT_SFAC);
    float* sL   = (float*)(su + AT_SL);

    const int tid  = threadIdx.x;
    const int wid  = tid >> 5;
    const int lane = tid & 31;
    const int g = lane >> 2;
    const int t = lane & 3;
    const int m0 = wid * 16;

    const int it  = (int)gridDim.x - 1 - (int)blockIdx.x;
    const int bh  = blockIdx.y;
    const int b   = bh / H_;
    const int h   = bh - b * H_;
    const int row0 = it * 128;

    const float* Q  = g_q + (size_t)bh * (S_ * D_) + (size_t)row0 * D_;
    const float* K0 = g_k + (size_t)bh * (S_ * D_);
    const float* V0 = g_v + (size_t)bh * (S_ * D_);
    const int* maskp = mask + b * S_;

    #pragma unroll
    for (int i = 0; i < 8; i++) {
        const int idx = tid + i * 256;
        const int r = idx >> 4, c4 = (idx & 15) << 2;
        float4 v = *(const float4*)(Q + r * D_ + c4);
        sQ[r][c4 + 0] = f2tf32(v.x * QSCALE);
        sQ[r][c4 + 1] = f2tf32(v.y * QSCALE);
        sQ[r][c4 + 2] = f2tf32(v.z * QSCALE);
        sQ[r][c4 + 3] = f2tf32(v.w * QSCALE);
    }

    const int srow  = tid >> 1;
    const int scol0 = (tid & 1) << 4;
    const int growo = row0 + srow;
    float m_row = -1e30f, l_row = 0.f;

    float o[8][4];
    #pragma unroll
    for (int nv = 0; nv < 8; nv++)
        #pragma unroll
        for (int r = 0; r < 4; r++) o[nv][r] = 0.f;

    const int ntiles = 4 * it + 4;
    for (int jt = 0; jt < ntiles; jt++) {
        const int kb = jt * 32;
        __syncthreads();
        #pragma unroll
        for (int i = 0; i < 2; i++) {
            const int idx = tid + i * 256;
            const int r = idx >> 4, c4 = (idx & 15) << 2;
            float4 kv = *(const float4*)(K0 + (size_t)(kb + r) * D_ + c4);
            float4 vv = *(const float4*)(V0 + (size_t)(kb + r) * D_ + c4);
            sK[r][c4 + 0] = f2tf32(kv.x);
            sK[r][c4 + 1] = f2tf32(kv.y);
            sK[r][c4 + 2] = f2tf32(kv.z);
            sK[r][c4 + 3] = f2tf32(kv.w);
            sV[r][c4 + 0] = f2tf32(vv.x);
            sV[r][c4 + 1] = f2tf32(vv.y);
            sV[r][c4 + 2] = f2tf32(vv.z);
            sV[r][c4 + 3] = f2tf32(vv.w);
        }
        __syncthreads();

        float sacc[4][4];
        #pragma unroll
        for (int nt = 0; nt < 4; nt++)
            #pragma unroll
            for (int r = 0; r < 4; r++) sacc[nt][r] = 0.f;

        #pragma unroll
        for (int ks = 0; ks < 8; ks++) {
            const int kc = ks * 8;
            uint32_t af[4];
            af[0] = sQ[m0 + g][kc + t];
            af[1] = sQ[m0 + g + 8][kc + t];
            af[2] = sQ[m0 + g][kc + t + 4];
            af[3] = sQ[m0 + g + 8][kc + t + 4];
            #pragma unroll
            for (int nt = 0; nt < 4; nt++) {
                uint32_t bf[2];
                bf[0] = sK[nt * 8 + g][kc + t];
                bf[1] = sK[nt * 8 + g][kc + t + 4];
                mma_tf32(sacc[nt], af, bf);
            }
        }

        #pragma unroll
        for (int nt = 0; nt < 4; nt++) {
            const int col = nt * 8 + 2 * t;
            *(float2*)&sSP[m0 + g][col] =
                make_float2(sacc[nt][0], sacc[nt][1]);
            *(float2*)&sSP[m0 + g + 8][col] =
                make_float2(sacc[nt][2], sacc[nt][3]);
        }
        __syncthreads();

        {
            float sv[16];
            int   km[16];
            #pragma unroll
            for (int j4 = 0; j4 < 4; j4++)
                *(int4*)&km[j4 * 4] =
                    *(const int4*)(maskp + kb + scol0 + j4 * 4);
            #pragma unroll
            for (int j = 0; j < 16; j++) {
                const int col = kb + scol0 + j;
                const bool ok = (col <= growo) && (km[j] != 0);
                sv[j] = ok ? sSP[srow][scol0 + j] : -1e30f;
            }
            float lm = sv[0];
            #pragma unroll
            for (int j = 1; j < 16; j++) lm = fmaxf(lm, sv[j]);
            lm = fmaxf(lm, __shfl_xor_sync(0xffffffffu, lm, 1));
            const float mnew = fmaxf(fmaxf(m_row, lm), -50.0f);
            const float fac = fexp2(m_row - mnew);
            float rs = 0.f;
            #pragma unroll
            for (int j = 0; j < 16; j++) {
                const float p = fexp2(sv[j] - mnew);
                rs += p;
                sSP[srow][scol0 + j] = p;
            }
            rs += __shfl_xor_sync(0xffffffffu, rs, 1);
            l_row = l_row * fac + rs;
            m_row = mnew;
            if ((tid & 1) == 0) sFac[srow] = fac;
        }
        __syncthreads();

        const float f0 = sFac[m0 + g];
        const float f1 = sFac[m0 + g + 8];
        #pragma unroll
        for (int nv = 0; nv < 8; nv++) {
            o[nv][0] *= f0; o[nv][1] *= f0;
            o[nv][2] *= f1; o[nv][3] *= f1;
        }

        #pragma unroll
        for (int ks = 0; ks < 4; ks++) {
            const int kc = ks * 8;
            uint32_t af[4];
            af[0] = __float_as_uint(sSP[m0 + g][kc + t]);
            af[1] = __float_as_uint(sSP[m0 + g + 8][kc + t]);
            af[2] = __float_as_uint(sSP[m0 + g][kc + t + 4]);
            af[3] = __float_as_uint(sSP[m0 + g + 8][kc + t + 4]);
            #pragma unroll
            for (int nv = 0; nv < 8; nv++) {
                uint32_t bf[2];
                bf[0] = sV[kc + t][nv * 8 + g];
                bf[1] = sV[kc + t + 4][nv * 8 + g];
                mma_tf32(o[nv], af, bf);
            }
        }
    }

    if ((tid & 1) == 0) sL[srow] = l_row;
    __syncthreads();

    const int gr0 = row0 + m0 + g;
    const int gr1 = gr0 + 8;
    const float lv0 = sL[m0 + g];
    const float lv1 = sL[m0 + g + 8];
    const float inv0 = (lv0 > 0.f) ? (1.f / lv0) : 0.f;
    const float inv1 = (lv1 > 0.f) ? (1.f / lv1) : 0.f;
    float* y0 = g_y + (size_t)(b * S_ + gr0) * C_ + h * D_;
    float* y1 = g_y + (size_t)(b * S_ + gr1) * C_ + h * D_;
    #pragma unroll
    for (int nv = 0; nv < 8; nv++) {
        const int col = nv * 8 + 2 * t;
        *(float2*)(y0 + col) = make_float2(o[nv][0] * inv0, o[nv][1] * inv0);
        *(float2*)(y1 + col) = make_float2(o[nv][2] * inv1, o[nv][3] * inv1);
    }
}

// ---------------------------------------------------------------------------
extern "C" void kernel_launch(void* const* d_in, const int* in_sizes, int n_in,
                              void* d_out, int out_size)
{
    const float* x      = (const float*)d_in[0];
    const float* w_qkv  = (const float*)d_in[1];
    const float* b_qkv  = (const float*)d_in[2];
    const float* w_out  = (const float*)d_in[3];
    const float* b_out  = (const float*)d_in[4];
    const int*   amask  = (const int*)d_in[5];
    float* out = (float*)d_out;

    cudaFuncSetAttribute(mmagemm_pipe0,
                         cudaFuncAttributeMaxDynamicSharedMemorySize,
                         GEMM_SMEM_BYTES);
    cudaFuncSetAttribute(attn_mma,
                         cudaFuncAttributeMaxDynamicSharedMemorySize,
                         AT_SMEM_BYTES);

    // 1) QKV projection (pipelined mma tf32) -> g_q/g_k/g_v [B,H,S,D]
    {
        dim3 grid((3 * C_) / 128, BS_ / 128);   // (18, 64)
        mmagemm_pipe0<<<grid, 256, GEMM_SMEM_BYTES>>>(x, w_qkv, b_qkv);
    }
    // 2) Flash attention (mma QK^T + SIMT softmax + mma PV) -> g_y
    {
        dim3 grid(S_ / 128, B_ * H_);           // (8, 96)
        attn_mma<<<grid, 256, AT_SMEM_BYTES>>>(amask);
    }
    // 3) Output projection (single-buffered mma tf32, R8 version) -> d_out
    {
        dim3 grid(C_ / 128, BS_ / 128);         // (6, 64)
        mmagemm_sb1<<<grid, 256>>>(w_out, b_out, out);
    }
}

// round 12
// speedup vs baseline: 1.4865x; 1.4865x over previous
#include <cuda_runtime.h>
#include <cstdint>

// Problem constants
#define B_  8
#define S_  1024
#define C_  768
#define H_  12
#define D_  64
#define BS_ (B_ * S_)            // 8192
#define BHSD (B_ * H_ * S_ * D_) // 6291456

// Scratch (allocation-free: static device globals)
__device__ float g_q[BHSD];
__device__ float g_k[BHSD];
__device__ float g_v[BHSD];
__device__ float g_y[BS_ * C_];

// ---------------------------------------------------------------------------
// mma.sync tf32 helpers (base sm_103 ISA)
// ---------------------------------------------------------------------------
__device__ __forceinline__ uint32_t f2tf32(float f) {
    uint32_t r;
    asm("cvt.rna.tf32.f32 %0, %1;" : "=r"(r) : "f"(f));
    return r;
}
__device__ __forceinline__ float fexp2(float x) {
    float y;
    asm("ex2.approx.f32 %0, %1;" : "=f"(y) : "f"(x));
    return y;
}
__device__ __forceinline__ void mma_tf32(float* c, const uint32_t* a,
                                         const uint32_t* b) {
    asm volatile(
        "mma.sync.aligned.m16n8k8.row.col.f32.tf32.tf32.f32 "
        "{%0,%1,%2,%3}, {%4,%5,%6,%7}, {%8,%9}, {%0,%1,%2,%3};"
        : "+f"(c[0]), "+f"(c[1]), "+f"(c[2]), "+f"(c[3])
        : "r"(a[0]), "r"(a[1]), "r"(a[2]), "r"(a[3]), "r"(b[0]), "r"(b[1]));
}
__device__ __forceinline__ void sts_tf32(uint32_t* dst, float4 v) {
    uint4 u = make_uint4(f2tf32(v.x), f2tf32(v.y), f2tf32(v.z), f2tf32(v.w));
    *(uint4*)dst = u;
}

// ===========================================================================
// Tensor-core GEMM NT, single-buffered (R8 structure), BK = 64.
// C[m,n] = sum_k A[m,k]*B[n,k] + bias[n]. 128x128 CTA tile, 8 warps (2x4),
// warp tile 64x32, mma m16n8k8 tf32. 12 chunks x (stage + 8 k-steps).
// MODE 0: A = x, scatter to g_q/g_k/g_v; MODE 1: A = g_y -> Cout.
// smem (dynamic): A[128][68] + B[128][68] u32 = 69632 bytes.
// ===========================================================================
#define BKW 68                         // row stride in words
#define GW  (128 * BKW)                // words per matrix
#define GEMM_SMEM_BYTES (2 * GW * 4)   // 69632
#define NKC64 (C_ / 64)                // 12 chunks

template <int MODE>
__global__ __launch_bounds__(256) void mmagemm(
    const float* __restrict__ Ain, const float* __restrict__ Bm,
    const float* __restrict__ bias, float* __restrict__ Cout)
{
    extern __shared__ uint32_t sg[];
    uint32_t* As = sg;
    uint32_t* Bs = sg + GW;

    const float* A = (MODE == 1) ? (const float*)g_y : Ain;

    const int tid  = threadIdx.x;
    const int wid  = tid >> 5;
    const int lane = tid & 31;
    const int g = lane >> 2;
    const int t = lane & 3;
    const int wr = (wid >> 2) * 64;
    const int wc = (wid & 3) * 32;
    const int bm = blockIdx.y * 128;
    const int bn = blockIdx.x * 128;

    float acc[4][4][4];
    #pragma unroll
    for (int i = 0; i < 4; i++)
        #pragma unroll
        for (int j = 0; j < 4; j++)
            #pragma unroll
            for (int r = 0; r < 4; r++) acc[i][j][r] = 0.f;

    for (int kc = 0; kc < NKC64; kc++) {
        const int k0 = kc * 64;
        // Stage A/B chunks: 128 rows x 64 fp32 each (8 float4 per thread per mat)
        #pragma unroll
        for (int i = 0; i < 8; i++) {
            const int idx = tid + i * 256;       // 0..2047
            const int row = idx >> 4;            // 0..127
            const int f4  = (idx & 15) << 2;     // 0,4,..,60
            float4 va = *(const float4*)(A  + (size_t)(bm + row) * C_ + k0 + f4);
            float4 vb = *(const float4*)(Bm + (size_t)(bn + row) * C_ + k0 + f4);
            sts_tf32(As + row * BKW + f4, va);
            sts_tf32(Bs + row * BKW + f4, vb);
        }
        __syncthreads();

        #pragma unroll
        for (int ks = 0; ks < 8; ks++) {
            const int kk = ks * 8;
            uint32_t af[4][4], bf[4][2];
            #pragma unroll
            for (int mt = 0; mt < 4; mt++) {
                const int r = wr + mt * 16 + g;
                af[mt][0] = As[r * BKW + kk + t];
                af[mt][1] = As[(r + 8) * BKW + kk + t];
                af[mt][2] = As[r * BKW + kk + t + 4];
                af[mt][3] = As[(r + 8) * BKW + kk + t + 4];
            }
            #pragma unroll
            for (int nt = 0; nt < 4; nt++) {
                const int n = wc + nt * 8 + g;
                bf[nt][0] = Bs[n * BKW + kk + t];
                bf[nt][1] = Bs[n * BKW + kk + t + 4];
            }
            #pragma unroll
            for (int mt = 0; mt < 4; mt++)
                #pragma unroll
                for (int nt = 0; nt < 4; nt++)
                    mma_tf32(acc[mt][nt], af[mt], bf[nt]);
        }
        __syncthreads();
    }

    // Epilogue (validated)
    #pragma unroll
    for (int mt = 0; mt < 4; mt++) {
        #pragma unroll
        for (int nt = 0; nt < 4; nt++) {
            const int col = wc + nt * 8 + 2 * t;
            const int r0  = bm + wr + mt * 16 + g;
            const int r1  = r0 + 8;
            const float bv0 = bias[bn + col];
            const float bv1 = bias[bn + col + 1];
            float2 lo = make_float2(acc[mt][nt][0] + bv0, acc[mt][nt][1] + bv1);
            float2 hi = make_float2(acc[mt][nt][2] + bv0, acc[mt][nt][3] + bv1);
            if (MODE == 0) {
                const int comp = bn / C_;
                float* db = (comp == 0) ? g_q : (comp == 1) ? g_k : g_v;
                const int c = bn - comp * C_ + col;
                const int h = c >> 6, d = c & 63;
                {
                    const int b = r0 >> 10, s = r0 & 1023;
                    *(float2*)(db + (size_t)(b * H_ + h) * (S_ * D_) +
                               (size_t)s * D_ + d) = lo;
                }
                {
                    const int b = r1 >> 10, s = r1 & 1023;
                    *(float2*)(db + (size_t)(b * H_ + h) * (S_ * D_) +
                               (size_t)s * D_ + d) = hi;
                }
            } else {
                *(float2*)(Cout + (size_t)r0 * C_ + bn + col) = lo;
                *(float2*)(Cout + (size_t)r1 * C_ + bn + col) = hi;
            }
        }
    }
}

// ===========================================================================
// Flash attention (unchanged from R8 — passing): mma QK^T -> S spill ->
// in-place SIMT softmax -> mma P@V. grid (8, 96), 256 threads.
// ===========================================================================
#define AT_SQ   0
#define AT_SK   (128 * 68)
#define AT_SV   (AT_SK + 32 * 68)
#define AT_SS   (AT_SV + 32 * 72)
#define AT_SFAC (AT_SS + 128 * 36)
#define AT_SL   (AT_SFAC + 128)
#define AT_SMEM_WORDS (AT_SL + 128)
#define AT_SMEM_BYTES (AT_SMEM_WORDS * 4)       // 72192
#define QSCALE 0.18033688011f                   // 0.125 * log2(e)

__global__ __launch_bounds__(256) void attn_mma(const int* __restrict__ mask)
{
    extern __shared__ uint32_t su[];
    uint32_t (*sQ)[68]  = (uint32_t(*)[68])(su + AT_SQ);
    uint32_t (*sK)[68]  = (uint32_t(*)[68])(su + AT_SK);
    uint32_t (*sV)[72]  = (uint32_t(*)[72])(su + AT_SV);
    float    (*sSP)[36] = (float(*)[36])(su + AT_SS);
    float* sFac = (float*)(su + AT_SFAC);
    float* sL   = (float*)(su + AT_SL);

    const int tid  = threadIdx.x;
    const int wid  = tid >> 5;
    const int lane = tid & 31;
    const int g = lane >> 2;
    const int t = lane & 3;
    const int m0 = wid * 16;

    const int it  = (int)gridDim.x - 1 - (int)blockIdx.x;
    const int bh  = blockIdx.y;
    const int b   = bh / H_;
    const int h   = bh - b * H_;
    const int row0 = it * 128;

    const float* Q  = g_q + (size_t)bh * (S_ * D_) + (size_t)row0 * D_;
    const float* K0 = g_k + (size_t)bh * (S_ * D_);
    const float* V0 = g_v + (size_t)bh * (S_ * D_);
    const int* maskp = mask + b * S_;

    #pragma unroll
    for (int i = 0; i < 8; i++) {
        const int idx = tid + i * 256;
        const int r = idx >> 4, c4 = (idx & 15) << 2;
        float4 v = *(const float4*)(Q + r * D_ + c4);
        sQ[r][c4 + 0] = f2tf32(v.x * QSCALE);
        sQ[r][c4 + 1] = f2tf32(v.y * QSCALE);
        sQ[r][c4 + 2] = f2tf32(v.z * QSCALE);
        sQ[r][c4 + 3] = f2tf32(v.w * QSCALE);
    }

    const int srow  = tid >> 1;
    const int scol0 = (tid & 1) << 4;
    const int growo = row0 + srow;
    float m_row = -1e30f, l_row = 0.f;

    float o[8][4];
    #pragma unroll
    for (int nv = 0; nv < 8; nv++)
        #pragma unroll
        for (int r = 0; r < 4; r++) o[nv][r] = 0.f;

    const int ntiles = 4 * it + 4;
    for (int jt = 0; jt < ntiles; jt++) {
        const int kb = jt * 32;
        __syncthreads();
        #pragma unroll
        for (int i = 0; i < 2; i++) {
            const int idx = tid + i * 256;
            const int r = idx >> 4, c4 = (idx & 15) << 2;
            float4 kv = *(const float4*)(K0 + (size_t)(kb + r) * D_ + c4);
            float4 vv = *(const float4*)(V0 + (size_t)(kb + r) * D_ + c4);
            sK[r][c4 + 0] = f2tf32(kv.x);
            sK[r][c4 + 1] = f2tf32(kv.y);
            sK[r][c4 + 2] = f2tf32(kv.z);
            sK[r][c4 + 3] = f2tf32(kv.w);
            sV[r][c4 + 0] = f2tf32(vv.x);
            sV[r][c4 + 1] = f2tf32(vv.y);
            sV[r][c4 + 2] = f2tf32(vv.z);
            sV[r][c4 + 3] = f2tf32(vv.w);
        }
        __syncthreads();

        float sacc[4][4];
        #pragma unroll
        for (int nt = 0; nt < 4; nt++)
            #pragma unroll
            for (int r = 0; r < 4; r++) sacc[nt][r] = 0.f;

        #pragma unroll
        for (int ks = 0; ks < 8; ks++) {
            const int kc = ks * 8;
            uint32_t af[4];
            af[0] = sQ[m0 + g][kc + t];
            af[1] = sQ[m0 + g + 8][kc + t];
            af[2] = sQ[m0 + g][kc + t + 4];
            af[3] = sQ[m0 + g + 8][kc + t + 4];
            #pragma unroll
            for (int nt = 0; nt < 4; nt++) {
                uint32_t bf[2];
                bf[0] = sK[nt * 8 + g][kc + t];
                bf[1] = sK[nt * 8 + g][kc + t + 4];
                mma_tf32(sacc[nt], af, bf);
            }
        }

        #pragma unroll
        for (int nt = 0; nt < 4; nt++) {
            const int col = nt * 8 + 2 * t;
            *(float2*)&sSP[m0 + g][col] =
                make_float2(sacc[nt][0], sacc[nt][1]);
            *(float2*)&sSP[m0 + g + 8][col] =
                make_float2(sacc[nt][2], sacc[nt][3]);
        }
        __syncthreads();

        {
            float sv[16];
            int   km[16];
            #pragma unroll
            for (int j4 = 0; j4 < 4; j4++)
                *(int4*)&km[j4 * 4] =
                    *(const int4*)(maskp + kb + scol0 + j4 * 4);
            #pragma unroll
            for (int j = 0; j < 16; j++) {
                const int col = kb + scol0 + j;
                const bool ok = (col <= growo) && (km[j] != 0);
                sv[j] = ok ? sSP[srow][scol0 + j] : -1e30f;
            }
            float lm = sv[0];
            #pragma unroll
            for (int j = 1; j < 16; j++) lm = fmaxf(lm, sv[j]);
            lm = fmaxf(lm, __shfl_xor_sync(0xffffffffu, lm, 1));
            const float mnew = fmaxf(fmaxf(m_row, lm), -50.0f);
            const float fac = fexp2(m_row - mnew);
            float rs = 0.f;
            #pragma unroll
            for (int j = 0; j < 16; j++) {
                const float p = fexp2(sv[j] - mnew);
                rs += p;
                sSP[srow][scol0 + j] = p;
            }
            rs += __shfl_xor_sync(0xffffffffu, rs, 1);
            l_row = l_row * fac + rs;
            m_row = mnew;
            if ((tid & 1) == 0) sFac[srow] = fac;
        }
        __syncthreads();

        const float f0 = sFac[m0 + g];
        const float f1 = sFac[m0 + g + 8];
        #pragma unroll
        for (int nv = 0; nv < 8; nv++) {
            o[nv][0] *= f0; o[nv][1] *= f0;
            o[nv][2] *= f1; o[nv][3] *= f1;
        }

        #pragma unroll
        for (int ks = 0; ks < 4; ks++) {
            const int kc = ks * 8;
            uint32_t af[4];
            af[0] = __float_as_uint(sSP[m0 + g][kc + t]);
            af[1] = __float_as_uint(sSP[m0 + g + 8][kc + t]);
            af[2] = __float_as_uint(sSP[m0 + g][kc + t + 4]);
            af[3] = __float_as_uint(sSP[m0 + g + 8][kc + t + 4]);
            #pragma unroll
            for (int nv = 0; nv < 8; nv++) {
                uint32_t bf[2];
                bf[0] = sV[kc + t][nv * 8 + g];
                bf[1] = sV[kc + t + 4][nv * 8 + g];
                mma_tf32(o[nv], af, bf);
            }
        }
    }

    if ((tid & 1) == 0) sL[srow] = l_row;
    __syncthreads();

    const int gr0 = row0 + m0 + g;
    const int gr1 = gr0 + 8;
    const float lv0 = sL[m0 + g];
    const float lv1 = sL[m0 + g + 8];
    const float inv0 = (lv0 > 0.f) ? (1.f / lv0) : 0.f;
    const float inv1 = (lv1 > 0.f) ? (1.f / lv1) : 0.f;
    float* y0 = g_y + (size_t)(b * S_ + gr0) * C_ + h * D_;
    float* y1 = g_y + (size_t)(b * S_ + gr1) * C_ + h * D_;
    #pragma unroll
    for (int nv = 0; nv < 8; nv++) {
        const int col = nv * 8 + 2 * t;
        *(float2*)(y0 + col) = make_float2(o[nv][0] * inv0, o[nv][1] * inv0);
        *(float2*)(y1 + col) = make_float2(o[nv][2] * inv1, o[nv][3] * inv1);
    }
}

// ---------------------------------------------------------------------------
extern "C" void kernel_launch(void* const* d_in, const int* in_sizes, int n_in,
                              void* d_out, int out_size)
{
    const float* x      = (const float*)d_in[0];
    const float* w_qkv  = (const float*)d_in[1];
    const float* b_qkv  = (const float*)d_in[2];
    const float* w_out  = (const float*)d_in[3];
    const float* b_out  = (const float*)d_in[4];
    const int*   amask  = (const int*)d_in[5];
    float* out = (float*)d_out;

    cudaFuncSetAttribute(mmagemm<0>,
                         cudaFuncAttributeMaxDynamicSharedMemorySize,
                         GEMM_SMEM_BYTES);
    cudaFuncSetAttribute(mmagemm<1>,
                         cudaFuncAttributeMaxDynamicSharedMemorySize,
                         GEMM_SMEM_BYTES);
    cudaFuncSetAttribute(attn_mma,
                         cudaFuncAttributeMaxDynamicSharedMemorySize,
                         AT_SMEM_BYTES);

    // 1) QKV projection (mma tf32, BK=64) -> g_q/g_k/g_v [B,H,S,D]
    {
        dim3 grid((3 * C_) / 128, BS_ / 128);   // (18, 64)
        mmagemm<0><<<grid, 256, GEMM_SMEM_BYTES>>>(x, w_qkv, b_qkv, nullptr);
    }
    // 2) Flash attention (mma QK^T + SIMT softmax + mma PV) -> g_y
    {
        dim3 grid(S_ / 128, B_ * H_);           // (8, 96)
        attn_mma<<<grid, 256, AT_SMEM_BYTES>>>(amask);
    }
    // 3) Output projection (mma tf32, BK=64) -> d_out
    {
        dim3 grid(C_ / 128, BS_ / 128);         // (6, 64)
        mmagemm<1><<<grid, 256, GEMM_SMEM_BYTES>>>(nullptr, w_out, b_out, out);
    }
}

// round 13
// speedup vs baseline: 1.5553x; 1.0463x over previous
#include <cuda_runtime.h>
#include <cstdint>

// Problem constants
#define B_  8
#define S_  1024
#define C_  768
#define H_  12
#define D_  64
#define BS_ (B_ * S_)            // 8192
#define BHSD (B_ * H_ * S_ * D_) // 6291456

// Scratch (allocation-free: static device globals)
__device__ float g_q[BHSD];
__device__ float g_k[BHSD];
__device__ float g_v[BHSD];
__device__ float g_y[BS_ * C_];
// tf32-preconverted operands (bits stored as float)
__device__ float g_xc[BS_ * C_];
__device__ float g_wqc[3 * C_ * C_];
__device__ float g_woc[C_ * C_];

// ---------------------------------------------------------------------------
// helpers
// ---------------------------------------------------------------------------
__device__ __forceinline__ uint32_t f2tf32(float f) {
    uint32_t r;
    asm("cvt.rna.tf32.f32 %0, %1;" : "=r"(r) : "f"(f));
    return r;
}
__device__ __forceinline__ float fexp2(float x) {
    float y;
    asm("ex2.approx.f32 %0, %1;" : "=f"(y) : "f"(x));
    return y;
}
__device__ __forceinline__ void mma_tf32(float* c, const uint32_t* a,
                                         const uint32_t* b) {
    asm volatile(
        "mma.sync.aligned.m16n8k8.row.col.f32.tf32.tf32.f32 "
        "{%0,%1,%2,%3}, {%4,%5,%6,%7}, {%8,%9}, {%0,%1,%2,%3};"
        : "+f"(c[0]), "+f"(c[1]), "+f"(c[2]), "+f"(c[3])
        : "r"(a[0]), "r"(a[1]), "r"(a[2]), "r"(a[3]), "r"(b[0]), "r"(b[1]));
}
__device__ __forceinline__ uint32_t smem_u32(const void* p) {
    uint32_t a;
    asm("{ .reg .u64 t; cvta.to.shared.u64 t, %1; cvt.u32.u64 %0, t; }"
        : "=r"(a) : "l"(p));
    return a;
}
__device__ __forceinline__ void cp16(uint32_t saddr, const void* g) {
    asm volatile("cp.async.cg.shared.global [%0], [%1], 16;"
                 :: "r"(saddr), "l"(g) : "memory");
}
#define CP_COMMIT() asm volatile("cp.async.commit_group;" ::: "memory")
#define CP_WAIT1()  asm volatile("cp.async.wait_group 1;" ::: "memory")

// ===========================================================================
// Prep: convert x, w_qkv, w_out to tf32 bit patterns (stored as float)
// ===========================================================================
__global__ void prep_convert(const float* __restrict__ x,
                             const float* __restrict__ wq,
                             const float* __restrict__ wo)
{
    const int stride = gridDim.x * blockDim.x;
    const int i0 = blockIdx.x * blockDim.x + threadIdx.x;
    for (int j = i0; j < BS_ * C_ / 4; j += stride) {
        float4 v = ((const float4*)x)[j];
        ((uint4*)g_xc)[j] = make_uint4(f2tf32(v.x), f2tf32(v.y),
                                       f2tf32(v.z), f2tf32(v.w));
    }
    for (int j = i0; j < 3 * C_ * C_ / 4; j += stride) {
        float4 v = ((const float4*)wq)[j];
        ((uint4*)g_wqc)[j] = make_uint4(f2tf32(v.x), f2tf32(v.y),
                                        f2tf32(v.z), f2tf32(v.w));
    }
    for (int j = i0; j < C_ * C_ / 4; j += stride) {
        float4 v = ((const float4*)wo)[j];
        ((uint4*)g_woc)[j] = make_uint4(f2tf32(v.x), f2tf32(v.y),
                                        f2tf32(v.z), f2tf32(v.w));
    }
}

// ===========================================================================
// Tensor-core GEMM NT with cp.async double-buffered staging.
// Operands are pre-converted tf32 bits. BK=32, 2 stages, 24 chunks.
// 128x128 CTA tile, 8 warps (2x4), warp tile 64x32, mma m16n8k8 tf32.
// MODE 0: A = g_xc, B = g_wqc, scatter to g_q/g_k/g_v.
// MODE 1: A = g_y (tf32-rounded by attention), B = g_woc -> Cout.
// smem: 2 stages x (A[128][36] + B[128][36]) u32 = 73728 bytes.
// ===========================================================================
#define STW (128 * 36)                 // words per matrix per stage
#define GEMM_SMEM_BYTES (4 * STW * 4)  // 73728
#define NKC (C_ / 32)                  // 24

template <int MODE>
__global__ __launch_bounds__(256) void mmagemm(
    const float* __restrict__ bias, float* __restrict__ Cout)
{
    extern __shared__ uint32_t sg[];
    const uint32_t sbase = smem_u32(sg);

    const float* A = (MODE == 1) ? (const float*)g_y : (const float*)g_xc;
    const float* Bm = (MODE == 1) ? (const float*)g_woc : (const float*)g_wqc;

    const int tid  = threadIdx.x;
    const int wid  = tid >> 5;
    const int lane = tid & 31;
    const int g = lane >> 2;
    const int t = lane & 3;
    const int wr = (wid >> 2) * 64;
    const int wc = (wid & 3) * 32;
    const int bm = blockIdx.y * 128;
    const int bn = blockIdx.x * 128;

    // Staging coordinates: 4 float4 per thread per matrix (128x32 chunk)
    int soff[4];
    const float *Ap[4], *Bp[4];
    #pragma unroll
    for (int i = 0; i < 4; i++) {
        const int idx = tid + i * 256;      // 0..1023
        const int row = idx >> 3;           // 0..127
        const int f4  = (idx & 7) << 2;     // 0..28
        soff[i] = (row * 36 + f4) * 4;      // byte offset within a stage matrix
        Ap[i] = A  + (size_t)(bm + row) * C_ + f4;
        Bp[i] = Bm + (size_t)(bn + row) * C_ + f4;
    }

    float acc[4][4][4];
    #pragma unroll
    for (int i = 0; i < 4; i++)
        #pragma unroll
        for (int j = 0; j < 4; j++)
            #pragma unroll
            for (int r = 0; r < 4; r++) acc[i][j][r] = 0.f;

    // issue chunk c into stage c&1 (always commits a group)
    auto issue = [&](int c) {
        if (c < NKC) {
            const uint32_t ab = sbase + (uint32_t)(c & 1) * (2 * STW * 4);
            const uint32_t bb = ab + STW * 4;
            const int k0 = c * 32;
            #pragma unroll
            for (int i = 0; i < 4; i++) {
                cp16(ab + soff[i], Ap[i] + k0);
                cp16(bb + soff[i], Bp[i] + k0);
            }
        }
        CP_COMMIT();
    };

    issue(0);
    for (int kc = 0; kc < NKC; kc++) {
        issue(kc + 1);
        CP_WAIT1();
        __syncthreads();

        const uint32_t* As = sg + (kc & 1) * (2 * STW);
        const uint32_t* Bs = As + STW;
        #pragma unroll
        for (int ks = 0; ks < 4; ks++) {
            const int kk = ks * 8;
            uint32_t af[4][4], bf[4][2];
            #pragma unroll
            for (int mt = 0; mt < 4; mt++) {
                const int r = wr + mt * 16 + g;
                af[mt][0] = As[r * 36 + kk + t];
                af[mt][1] = As[(r + 8) * 36 + kk + t];
                af[mt][2] = As[r * 36 + kk + t + 4];
                af[mt][3] = As[(r + 8) * 36 + kk + t + 4];
            }
            #pragma unroll
            for (int nt = 0; nt < 4; nt++) {
                const int n = wc + nt * 8 + g;
                bf[nt][0] = Bs[n * 36 + kk + t];
                bf[nt][1] = Bs[n * 36 + kk + t + 4];
            }
            #pragma unroll
            for (int mt = 0; mt < 4; mt++)
                #pragma unroll
                for (int nt = 0; nt < 4; nt++)
                    mma_tf32(acc[mt][nt], af[mt], bf[nt]);
        }
        __syncthreads();
    }

    // Epilogue (validated)
    #pragma unroll
    for (int mt = 0; mt < 4; mt++) {
        #pragma unroll
        for (int nt = 0; nt < 4; nt++) {
            const int col = wc + nt * 8 + 2 * t;
            const int r0  = bm + wr + mt * 16 + g;
            const int r1  = r0 + 8;
            const float bv0 = bias[bn + col];
            const float bv1 = bias[bn + col + 1];
            float2 lo = make_float2(acc[mt][nt][0] + bv0, acc[mt][nt][1] + bv1);
            float2 hi = make_float2(acc[mt][nt][2] + bv0, acc[mt][nt][3] + bv1);
            if (MODE == 0) {
                const int comp = bn / C_;
                float* db = (comp == 0) ? g_q : (comp == 1) ? g_k : g_v;
                const int c = bn - comp * C_ + col;
                const int h = c >> 6, d = c & 63;
                {
                    const int b = r0 >> 10, s = r0 & 1023;
                    *(float2*)(db + (size_t)(b * H_ + h) * (S_ * D_) +
                               (size_t)s * D_ + d) = lo;
                }
                {
                    const int b = r1 >> 10, s = r1 & 1023;
                    *(float2*)(db + (size_t)(b * H_ + h) * (S_ * D_) +
                               (size_t)s * D_ + d) = hi;
                }
            } else {
                *(float2*)(Cout + (size_t)r0 * C_ + bn + col) = lo;
                *(float2*)(Cout + (size_t)r1 * C_ + bn + col) = hi;
            }
        }
    }
}

// ===========================================================================
// Flash attention (R8 structure, passing). Epilogue now writes g_y
// tf32-rounded so the output projection can stage it raw via cp.async.
// ===========================================================================
#define AT_SQ   0
#define AT_SK   (128 * 68)
#define AT_SV   (AT_SK + 32 * 68)
#define AT_SS   (AT_SV + 32 * 72)
#define AT_SFAC (AT_SS + 128 * 36)
#define AT_SL   (AT_SFAC + 128)
#define AT_SMEM_WORDS (AT_SL + 128)
#define AT_SMEM_BYTES (AT_SMEM_WORDS * 4)       // 72192
#define QSCALE 0.18033688011f                   // 0.125 * log2(e)

__global__ __launch_bounds__(256) void attn_mma(const int* __restrict__ mask)
{
    extern __shared__ uint32_t su[];
    uint32_t (*sQ)[68]  = (uint32_t(*)[68])(su + AT_SQ);
    uint32_t (*sK)[68]  = (uint32_t(*)[68])(su + AT_SK);
    uint32_t (*sV)[72]  = (uint32_t(*)[72])(su + AT_SV);
    float    (*sSP)[36] = (float(*)[36])(su + AT_SS);
    float* sFac = (float*)(su + AT_SFAC);
    float* sL   = (float*)(su + AT_SL);

    const int tid  = threadIdx.x;
    const int wid  = tid >> 5;
    const int lane = tid & 31;
    const int g = lane >> 2;
    const int t = lane & 3;
    const int m0 = wid * 16;

    const int it  = (int)gridDim.x - 1 - (int)blockIdx.x;
    const int bh  = blockIdx.y;
    const int b   = bh / H_;
    const int h   = bh - b * H_;
    const int row0 = it * 128;

    const float* Q  = g_q + (size_t)bh * (S_ * D_) + (size_t)row0 * D_;
    const float* K0 = g_k + (size_t)bh * (S_ * D_);
    const float* V0 = g_v + (size_t)bh * (S_ * D_);
    const int* maskp = mask + b * S_;

    #pragma unroll
    for (int i = 0; i < 8; i++) {
        const int idx = tid + i * 256;
        const int r = idx >> 4, c4 = (idx & 15) << 2;
        float4 v = *(const float4*)(Q + r * D_ + c4);
        sQ[r][c4 + 0] = f2tf32(v.x * QSCALE);
        sQ[r][c4 + 1] = f2tf32(v.y * QSCALE);
        sQ[r][c4 + 2] = f2tf32(v.z * QSCALE);
        sQ[r][c4 + 3] = f2tf32(v.w * QSCALE);
    }

    const int srow  = tid >> 1;
    const int scol0 = (tid & 1) << 4;
    const int growo = row0 + srow;
    float m_row = -1e30f, l_row = 0.f;

    float o[8][4];
    #pragma unroll
    for (int nv = 0; nv < 8; nv++)
        #pragma unroll
        for (int r = 0; r < 4; r++) o[nv][r] = 0.f;

    const int ntiles = 4 * it + 4;
    for (int jt = 0; jt < ntiles; jt++) {
        const int kb = jt * 32;
        __syncthreads();
        #pragma unroll
        for (int i = 0; i < 2; i++) {
            const int idx = tid + i * 256;
            const int r = idx >> 4, c4 = (idx & 15) << 2;
            float4 kv = *(const float4*)(K0 + (size_t)(kb + r) * D_ + c4);
            float4 vv = *(const float4*)(V0 + (size_t)(kb + r) * D_ + c4);
            sK[r][c4 + 0] = f2tf32(kv.x);
            sK[r][c4 + 1] = f2tf32(kv.y);
            sK[r][c4 + 2] = f2tf32(kv.z);
            sK[r][c4 + 3] = f2tf32(kv.w);
            sV[r][c4 + 0] = f2tf32(vv.x);
            sV[r][c4 + 1] = f2tf32(vv.y);
            sV[r][c4 + 2] = f2tf32(vv.z);
            sV[r][c4 + 3] = f2tf32(vv.w);
        }
        __syncthreads();

        float sacc[4][4];
        #pragma unroll
        for (int nt = 0; nt < 4; nt++)
            #pragma unroll
            for (int r = 0; r < 4; r++) sacc[nt][r] = 0.f;

        #pragma unroll
        for (int ks = 0; ks < 8; ks++) {
            const int kc = ks * 8;
            uint32_t af[4];
            af[0] = sQ[m0 + g][kc + t];
            af[1] = sQ[m0 + g + 8][kc + t];
            af[2] = sQ[m0 + g][kc + t + 4];
            af[3] = sQ[m0 + g + 8][kc + t + 4];
            #pragma unroll
            for (int nt = 0; nt < 4; nt++) {
                uint32_t bf[2];
                bf[0] = sK[nt * 8 + g][kc + t];
                bf[1] = sK[nt * 8 + g][kc + t + 4];
                mma_tf32(sacc[nt], af, bf);
            }
        }

        #pragma unroll
        for (int nt = 0; nt < 4; nt++) {
            const int col = nt * 8 + 2 * t;
            *(float2*)&sSP[m0 + g][col] =
                make_float2(sacc[nt][0], sacc[nt][1]);
            *(float2*)&sSP[m0 + g + 8][col] =
                make_float2(sacc[nt][2], sacc[nt][3]);
        }
        __syncthreads();

        {
            float sv[16];
            int   km[16];
            #pragma unroll
            for (int j4 = 0; j4 < 4; j4++)
                *(int4*)&km[j4 * 4] =
                    *(const int4*)(maskp + kb + scol0 + j4 * 4);
            #pragma unroll
            for (int j = 0; j < 16; j++) {
                const int col = kb + scol0 + j;
                const bool ok = (col <= growo) && (km[j] != 0);
                sv[j] = ok ? sSP[srow][scol0 + j] : -1e30f;
            }
            float lm = sv[0];
            #pragma unroll
            for (int j = 1; j < 16; j++) lm = fmaxf(lm, sv[j]);
            lm = fmaxf(lm, __shfl_xor_sync(0xffffffffu, lm, 1));
            const float mnew = fmaxf(fmaxf(m_row, lm), -50.0f);
            const float fac = fexp2(m_row - mnew);
            float rs = 0.f;
            #pragma unroll
            for (int j = 0; j < 16; j++) {
                const float p = fexp2(sv[j] - mnew);
                rs += p;
                sSP[srow][scol0 + j] = p;
            }
            rs += __shfl_xor_sync(0xffffffffu, rs, 1);
            l_row = l_row * fac + rs;
            m_row = mnew;
            if ((tid & 1) == 0) sFac[srow] = fac;
        }
        __syncthreads();

        const float f0 = sFac[m0 + g];
        const float f1 = sFac[m0 + g + 8];
        #pragma unroll
        for (int nv = 0; nv < 8; nv++) {
            o[nv][0] *= f0; o[nv][1] *= f0;
            o[nv][2] *= f1; o[nv][3] *= f1;
        }

        #pragma unroll
        for (int ks = 0; ks < 4; ks++) {
            const int kc = ks * 8;
            uint32_t af[4];
            af[0] = __float_as_uint(sSP[m0 + g][kc + t]);
            af[1] = __float_as_uint(sSP[m0 + g + 8][kc + t]);
            af[2] = __float_as_uint(sSP[m0 + g][kc + t + 4]);
            af[3] = __float_as_uint(sSP[m0 + g + 8][kc + t + 4]);
            #pragma unroll
            for (int nv = 0; nv < 8; nv++) {
                uint32_t bf[2];
                bf[0] = sV[kc + t][nv * 8 + g];
                bf[1] = sV[kc + t + 4][nv * 8 + g];
                mma_tf32(o[nv], af, bf);
            }
        }
    }

    if ((tid & 1) == 0) sL[srow] = l_row;
    __syncthreads();

    const int gr0 = row0 + m0 + g;
    const int gr1 = gr0 + 8;
    const float lv0 = sL[m0 + g];
    const float lv1 = sL[m0 + g + 8];
    const float inv0 = (lv0 > 0.f) ? (1.f / lv0) : 0.f;
    const float inv1 = (lv1 > 0.f) ? (1.f / lv1) : 0.f;
    float* y0 = g_y + (size_t)(b * S_ + gr0) * C_ + h * D_;
    float* y1 = g_y + (size_t)(b * S_ + gr1) * C_ + h * D_;
    #pragma unroll
    for (int nv = 0; nv < 8; nv++) {
        const int col = nv * 8 + 2 * t;
        // tf32-rounded so gemm1 can stage raw (rna is idempotent)
        *(float2*)(y0 + col) = make_float2(
            __uint_as_float(f2tf32(o[nv][0] * inv0)),
            __uint_as_float(f2tf32(o[nv][1] * inv0)));
        *(float2*)(y1 + col) = make_float2(
            __uint_as_float(f2tf32(o[nv][2] * inv1)),
            __uint_as_float(f2tf32(o[nv][3] * inv1)));
    }
}

// ---------------------------------------------------------------------------
extern "C" void kernel_launch(void* const* d_in, const int* in_sizes, int n_in,
                              void* d_out, int out_size)
{
    const float* x      = (const float*)d_in[0];
    const float* w_qkv  = (const float*)d_in[1];
    const float* b_qkv  = (const float*)d_in[2];
    const float* w_out  = (const float*)d_in[3];
    const float* b_out  = (const float*)d_in[4];
    const int*   amask  = (const int*)d_in[5];
    float* out = (float*)d_out;

    cudaFuncSetAttribute(mmagemm<0>,
                         cudaFuncAttributeMaxDynamicSharedMemorySize,
                         GEMM_SMEM_BYTES);
    cudaFuncSetAttribute(mmagemm<1>,
                         cudaFuncAttributeMaxDynamicSharedMemorySize,
                         GEMM_SMEM_BYTES);
    cudaFuncSetAttribute(attn_mma,
                         cudaFuncAttributeMaxDynamicSharedMemorySize,
                         AT_SMEM_BYTES);

    // 0) Pre-convert operands to tf32 bit patterns
    prep_convert<<<592, 256>>>(x, w_qkv, w_out);
    // 1) QKV projection (cp.async pipelined mma tf32) -> g_q/g_k/g_v
    {
        dim3 grid((3 * C_) / 128, BS_ / 128);   // (18, 64)
        mmagemm<0><<<grid, 256, GEMM_SMEM_BYTES>>>(b_qkv, nullptr);
    }
    // 2) Flash attention (mma QK^T + SIMT softmax + mma PV) -> g_y (tf32)
    {
        dim3 grid(S_ / 128, B_ * H_);           // (8, 96)
        attn_mma<<<grid, 256, AT_SMEM_BYTES>>>(amask);
    }
    // 3) Output projection (cp.async pipelined mma tf32) -> d_out
    {
        dim3 grid(C_ / 128, BS_ / 128);         // (6, 64)
        mmagemm<1><<<grid, 256, GEMM_SMEM_BYTES>>>(b_out, out);
    }
}